// round 1
// baseline (speedup 1.0000x reference)
#include <cuda_runtime.h>
#include <cstdint>

// SigCubicalEcc: smoothed Euler characteristic curve of a T-construction
// cubical complex over 64x64 images. B=64, C=3, STEPS=32, LAM=200.
//
// Unified cell grid: doubled coords (r,c) in [0,129)^2.
//   even/even = vertex (+), odd/odd = face (+), mixed = edge (-).
//   filtration f(r,c) = min over padded image xp[a][b],
//     a in {(r+1)>>1, (r>>1)+1}, b in {(c+1)>>1, (c>>1)+1}.
// ECC_j = sum_cells sign * sigmoid(LAM*(t_j - f)).

#define HH 64
#define WW 64
#define STEPS 32
#define NGRID 129              // 2*H+1
#define NCELLS (NGRID * NGRID) // 16641
#define SLICES 4
#define THREADS 128
#define PITCH 68               // smem row pitch (floats), 66 used
#define BIGV 1e9f

__device__ __forceinline__ float ex2_approx(float x) {
    float y;
    asm("ex2.approx.ftz.f32 %0, %1;" : "=f"(y) : "f"(x));
    return y;
}
__device__ __forceinline__ float rcp_approx(float x) {
    float y;
    asm("rcp.approx.ftz.f32 %0, %1;" : "=f"(y) : "f"(x));
    return y;
}

__global__ void zero_out_kernel(float* out, int n) {
    int i = blockIdx.x * blockDim.x + threadIdx.x;
    if (i < n) out[i] = 0.0f;
}

__global__ __launch_bounds__(THREADS)
void sig_cubical_ecc_kernel(const float* __restrict__ x, float* __restrict__ out,
                            int bc) {
    __shared__ float xp[66 * PITCH];
    __shared__ float red[THREADS / 32][STEPS];

    const int img   = blockIdx.x / SLICES;
    const int slice = blockIdx.x % SLICES;
    const int tid   = threadIdx.x;

    // ---- load image into padded smem ----
    for (int i = tid; i < 66 * PITCH; i += THREADS) xp[i] = BIGV;
    __syncthreads();
    const float* xi = x + (size_t)img * (HH * WW);
    for (int i = tid; i < HH * WW; i += THREADS) {
        int r = i >> 6;       // /64
        int c = i & 63;
        xp[(r + 1) * PITCH + (c + 1)] = xi[i];
    }
    __syncthreads();

    // ---- per-thread accumulators over the 32 t-steps ----
    float acc[STEPS];
#pragma unroll
    for (int j = 0; j < STEPS; j++) acc[j] = 0.0f;

    // K = LAM * log2(e); A_j = K * t_j with t_j = 0.02 + j*0.26/31
    const float K = 200.0f * 1.4426950408889634f;

    const int chunk = (NCELLS + SLICES - 1) / SLICES; // 4161
    const int beg = slice * chunk;
    const int end = (beg + chunk < NCELLS) ? (beg + chunk) : NCELLS;

    for (int cell = beg + tid; cell < end; cell += THREADS) {
        int r = cell / NGRID;
        int c = cell - r * NGRID;
        int lr = (r + 1) >> 1, hr = (r >> 1) + 1;
        int lc = (c + 1) >> 1, hc = (c >> 1) + 1;
        float f0 = xp[lr * PITCH + lc];
        float f1 = xp[lr * PITCH + hc];
        float f2 = xp[hr * PITCH + lc];
        float f3 = xp[hr * PITCH + hc];
        float f = fminf(fminf(f0, f1), fminf(f2, f3));
        float g = f * K;
        float sign = ((r ^ c) & 1) ? -1.0f : 1.0f;

#pragma unroll
        for (int j = 0; j < STEPS; j++) {
            float tj = 0.02f + (float)j * (0.26f / 31.0f);
            float Aj = K * tj;                 // compile-time constant
            float u = g - Aj;                  // FADD (imm)
            float e = ex2_approx(u);           // MUFU.EX2
            float d = 1.0f + e;                // FADD
            float s = rcp_approx(d);           // MUFU.RCP
            acc[j] = fmaf(sign, s, acc[j]);    // FFMA
        }
    }

    // ---- block reduction: warp shuffles, then cross-warp in smem ----
    const int lane = tid & 31;
    const int warp = tid >> 5;
#pragma unroll
    for (int j = 0; j < STEPS; j++) {
        float v = acc[j];
#pragma unroll
        for (int o = 16; o > 0; o >>= 1)
            v += __shfl_xor_sync(0xffffffffu, v, o);
        if (lane == 0) red[warp][j] = v;
    }
    __syncthreads();

    if (tid < STEPS) {
        float s = 0.0f;
#pragma unroll
        for (int w = 0; w < THREADS / 32; w++) s += red[w][tid];
        atomicAdd(&out[img * STEPS + tid], s);
    }
}

extern "C" void kernel_launch(void* const* d_in, const int* in_sizes, int n_in,
                              void* d_out, int out_size) {
    const float* x = (const float*)d_in[0];
    float* out = (float*)d_out;
    int bc = in_sizes[0] / (HH * WW);   // 192 images

    zero_out_kernel<<<(out_size + 255) / 256, 256>>>(out, out_size);
    sig_cubical_ecc_kernel<<<bc * SLICES, THREADS>>>(x, out, bc);
}

// round 2
// speedup vs baseline: 1.4716x; 1.4716x over previous
#include <cuda_runtime.h>
#include <cstdint>

// SigCubicalEcc: smoothed Euler characteristic curve of a T-construction
// cubical complex over 64x64 images. B=64, C=3, STEPS=32, LAM=200.
//
// Round 2: factor exp out of the step loop.
//   sigmoid(LAM*(t_j - f)) = rcp(1 + ex2(K*f) * 2^{-K*t_j}),  K = LAM*log2(e)
// => 1 EX2 per cell + 1 RCP per step (33 MUFU/cell vs 64 before).
// Overflow path is exact: ex2->inf, fma->inf, rcp.approx(inf)=0.

#define HH 64
#define WW 64
#define STEPS 32
#define NGRID 129              // 2*H+1
#define NCELLS (NGRID * NGRID) // 16641
#define SLICES 8
#define THREADS 128
#define PITCH 68               // smem row pitch (floats), 66 used
#define BIGV 1e9f

__device__ __forceinline__ float ex2_approx(float x) {
    float y;
    asm("ex2.approx.ftz.f32 %0, %1;" : "=f"(y) : "f"(x));
    return y;
}
__device__ __forceinline__ float rcp_approx(float x) {
    float y;
    asm("rcp.approx.ftz.f32 %0, %1;" : "=f"(y) : "f"(x));
    return y;
}

__global__ void zero_out_kernel(float* out, int n) {
    int i = blockIdx.x * blockDim.x + threadIdx.x;
    if (i < n) out[i] = 0.0f;
}

__global__ __launch_bounds__(THREADS)
void sig_cubical_ecc_kernel(const float* __restrict__ x, float* __restrict__ out) {
    __shared__ float xp[66 * PITCH];
    __shared__ float red[THREADS / 32][STEPS];

    const int img   = blockIdx.x / SLICES;
    const int slice = blockIdx.x % SLICES;
    const int tid   = threadIdx.x;

    // ---- load image into padded smem ----
    for (int i = tid; i < 66 * PITCH; i += THREADS) xp[i] = BIGV;
    __syncthreads();
    const float* xi = x + (size_t)img * (HH * WW);
    for (int i = tid; i < HH * WW; i += THREADS) {
        int r = i >> 6;       // /64
        int c = i & 63;
        xp[(r + 1) * PITCH + (c + 1)] = xi[i];
    }
    __syncthreads();

    // ---- per-thread accumulators over the 32 t-steps ----
    float acc[STEPS];
#pragma unroll
    for (int j = 0; j < STEPS; j++) acc[j] = 0.0f;

    // K = LAM * log2(e)
    const float K = 200.0f * 1.4426950408889634f;

    const int chunk = (NCELLS + SLICES - 1) / SLICES; // 2081
    const int beg = slice * chunk;
    const int end = (beg + chunk < NCELLS) ? (beg + chunk) : NCELLS;

    for (int cell = beg + tid; cell < end; cell += THREADS) {
        int r = cell / NGRID;
        int c = cell - r * NGRID;
        int lr = (r + 1) >> 1, hr = (r >> 1) + 1;
        int lc = (c + 1) >> 1, hc = (c >> 1) + 1;
        float f0 = xp[lr * PITCH + lc];
        float f1 = xp[lr * PITCH + hc];
        float f2 = xp[hr * PITCH + lc];
        float f3 = xp[hr * PITCH + hc];
        float f = fminf(fminf(f0, f1), fminf(f2, f3));
        float E = ex2_approx(f * K);          // once per cell
        float sign = ((r ^ c) & 1) ? -1.0f : 1.0f;

#pragma unroll
        for (int j = 0; j < STEPS; j++) {
            float tj = 0.02f + (float)j * (0.26f / 31.0f);
            // c_j = 2^{-K*t_j}, compile-time constant
            float cj = __uint_as_float(0);  // placeholder, replaced below
            // compute constant at compile time via constexpr-style arithmetic:
            cj = exp2f(-K * tj);            // folded to an immediate by nvcc
            float d = fmaf(E, cj, 1.0f);    // FFMA
            float s = rcp_approx(d);        // MUFU.RCP
            acc[j] = fmaf(sign, s, acc[j]); // FFMA
        }
    }

    // ---- block reduction: warp shuffles, then cross-warp in smem ----
    const int lane = tid & 31;
    const int warp = tid >> 5;
#pragma unroll
    for (int j = 0; j < STEPS; j++) {
        float v = acc[j];
#pragma unroll
        for (int o = 16; o > 0; o >>= 1)
            v += __shfl_xor_sync(0xffffffffu, v, o);
        if (lane == 0) red[warp][j] = v;
    }
    __syncthreads();

    if (tid < STEPS) {
        float s = 0.0f;
#pragma unroll
        for (int w = 0; w < THREADS / 32; w++) s += red[w][tid];
        atomicAdd(&out[img * STEPS + tid], s);
    }
}

extern "C" void kernel_launch(void* const* d_in, const int* in_sizes, int n_in,
                              void* d_out, int out_size) {
    const float* x = (const float*)d_in[0];
    float* out = (float*)d_out;
    int bc = in_sizes[0] / (HH * WW);   // 192 images

    zero_out_kernel<<<(out_size + 255) / 256, 256>>>(out, out_size);
    sig_cubical_ecc_kernel<<<bc * SLICES, THREADS>>>(x, out);
}

// round 3
// speedup vs baseline: 2.3449x; 1.5934x over previous
#include <cuda_runtime.h>
#include <cstdint>

// SigCubicalEcc round 3: per-PIXEL sigmoids + max-decomposition.
// sigma(lam*(t - min(pixels))) = max(per-pixel sigmas) since sigmoid is monotone.
// ECC_j = Sum_v max(m, m_up) - Sum_eh max(s, s_up) - Sum_ev m + Sum_f s
// with m[r][c] = max(s[r][c], s[r][c+1]) (zero padding outside the image),
// and (s0 + s1 - m0) = min(s0, s1).

#define HH 64
#define WW 64
#define STEPS 32
#define GROUPS 4               // step groups per image
#define SPG (STEPS / GROUPS)   // 8 steps per block
#define THREADS 128
#define NWARP 4
#define ROWS_PER_WARP 16

__device__ __forceinline__ float ex2_approx(float x) {
    float y;
    asm("ex2.approx.ftz.f32 %0, %1;" : "=f"(y) : "f"(x));
    return y;
}
__device__ __forceinline__ float rcp_approx(float x) {
    float y;
    asm("rcp.approx.ftz.f32 %0, %1;" : "=f"(y) : "f"(x));
    return y;
}

__global__ void zero_out_kernel(float* out, int n) {
    int i = blockIdx.x * blockDim.x + threadIdx.x;
    if (i < n) out[i] = 0.0f;
}

// Compute per-pixel sigmas and horizontal maxes for one row.
// Lane L owns columns 2L, 2L+1. snext comes from lane L+1 via shfl.
__device__ __forceinline__ void row_sig(const float* __restrict__ E, int r,
                                        float cj, int lane,
                                        float& s0, float& s1,
                                        float& m0, float& m1) {
    float2 e = *reinterpret_cast<const float2*>(E + r * WW + 2 * lane);
    s0 = rcp_approx(fmaf(e.x, cj, 1.0f));
    s1 = rcp_approx(fmaf(e.y, cj, 1.0f));
    float sn = __shfl_down_sync(0xffffffffu, s0, 1);
    sn = (lane == 31) ? 0.0f : sn;
    m0 = fmaxf(s0, s1);
    m1 = fmaxf(s1, sn);
}

__global__ __launch_bounds__(THREADS)
void sig_cubical_ecc_kernel(const float* __restrict__ x, float* __restrict__ out) {
    __shared__ float E[HH * WW];   // 16 KB: E = 2^(K*x)

    const int img   = blockIdx.x >> 2;        // / GROUPS
    const int group = blockIdx.x & (GROUPS - 1);
    const int tid   = threadIdx.x;
    const int lane  = tid & 31;
    const int warp  = tid >> 5;

    const float K = 200.0f * 1.4426950408889634f;  // LAM * log2(e)

    // ---- precompute E once per block ----
    const float* xi = x + (size_t)img * (HH * WW);
    for (int i = tid; i < HH * WW; i += THREADS)
        E[i] = ex2_approx(xi[i] * K);
    __syncthreads();

    const int r0 = warp * ROWS_PER_WARP;

    for (int jj = 0; jj < SPG; jj++) {
        const int j = group * SPG + jj;
        const float tj = 0.02f + (float)j * (0.26f / 31.0f);
        const float cj = ex2_approx(-K * tj);   // 2^(-K*t_j)

        // prev row (halo): row r0-1, or zeros for warp 0 (row -1 is padding)
        float sp0 = 0.0f, sp1 = 0.0f, mp0 = 0.0f, mp1 = 0.0f;
        if (warp > 0)
            row_sig(E, r0 - 1, cj, lane, sp0, sp1, mp0, mp1);

        float acc = 0.0f;
#pragma unroll 4
        for (int i = 0; i < ROWS_PER_WARP; i++) {
            const int r = r0 + i;
            float s0, s1, m0, m1;
            row_sig(E, r, cj, lane, s0, s1, m0, m1);

            float eh0 = fmaxf(s0, sp0);
            // lane 0: the c=-1 vertex term cancels the c=0 h-edge term,
            // leaving an extra -s0 from the c=-1 vertical edge.
            float ehsel = (lane == 0) ? s0 : eh0;
            float contrib = (fminf(s0, s1) - m1)
                          + (fmaxf(m0, mp0) - ehsel)
                          + (fmaxf(m1, mp1) - fmaxf(s1, sp1));
            acc += contrib;

            sp0 = s0; sp1 = s1; mp0 = m0; mp1 = m1;
        }

        // bottom padding row-pair (63, 64): handled by last warp. s=m=0 there.
        if (warp == NWARP - 1) {
            float ehsel = (lane == 0) ? 0.0f : sp0;
            acc += (mp0 - ehsel) + (mp1 - sp1);
        }

        // warp reduce + one atomic per (warp, step)
#pragma unroll
        for (int o = 16; o > 0; o >>= 1)
            acc += __shfl_xor_sync(0xffffffffu, acc, o);
        if (lane == 0)
            atomicAdd(&out[img * STEPS + j], acc);
    }
}

extern "C" void kernel_launch(void* const* d_in, const int* in_sizes, int n_in,
                              void* d_out, int out_size) {
    const float* x = (const float*)d_in[0];
    float* out = (float*)d_out;
    int bc = in_sizes[0] / (HH * WW);   // 192 images

    zero_out_kernel<<<(out_size + 255) / 256, 256>>>(out, out_size);
    sig_cubical_ecc_kernel<<<bc * GROUPS, THREADS>>>(x, out);
}